// round 2
// baseline (speedup 1.0000x reference)
#include <cuda_runtime.h>
#include <math.h>

// Problem constants
#define TT   131072   // tokens
#define D_IN 256      // input dim
#define HH   128      // per-direction hidden
#define G4   512      // 4*HH gate rows
#define HID  256      // bidirectional hidden
#define TAGS 10
#define NSEG 1024

// Scratch (device globals — no allocation allowed in kernel_launch)
__device__ float g_pre[2][TT][G4];   // pre-activations per direction (original token order)
__device__ float g_hs[TT][HID];      // [hf | hb] concatenated
__device__ float g_att[TT];          // attention logits

__device__ __forceinline__ float sigmoidf_(float x) {
    return 1.0f / (1.0f + __expf(-x));
}
// Accurate tanh via expf, safe at +/- inf of the exp
__device__ __forceinline__ float tanh_acc(float x) {
    return 1.0f - 2.0f / (__expf(2.0f * x) + 1.0f);
}

// ---------------------------------------------------------------------------
// Kernel A: pre[dir][t][g] = x[t] . w_ih[g] + b_ih[g] + b_hh[g]
// 64x64 tile, K=256, 256 threads, 4x4 register blocking.
// ---------------------------------------------------------------------------
__global__ __launch_bounds__(256) void gemm_pre_kernel(
    const float* __restrict__ x,
    const float* __restrict__ wf, const float* __restrict__ bif, const float* __restrict__ bhf,
    const float* __restrict__ wb, const float* __restrict__ bib, const float* __restrict__ bhb)
{
    int dir = blockIdx.z;
    const float* w  = dir ? wb  : wf;
    const float* b1 = dir ? bib : bif;
    const float* b2 = dir ? bhb : bhf;
    float* out = &g_pre[dir][0][0];

    int tok0 = blockIdx.x * 64;
    int g0   = blockIdx.y * 64;

    __shared__ float xs[16][64];
    __shared__ float wsm[16][64];

    int tid = threadIdx.x;
    int tx = tid & 15;        // gate group
    int ty = tid >> 4;        // token group

    float acc[4][4];
#pragma unroll
    for (int i = 0; i < 4; i++)
#pragma unroll
        for (int j = 0; j < 4; j++) acc[i][j] = 0.f;

    int lr = tid >> 2;          // 0..63 (row within tile)
    int lc = (tid & 3) * 4;     // 0,4,8,12 (k offset)

    for (int kk = 0; kk < D_IN; kk += 16) {
        float4 xv = *(const float4*)(x + (size_t)(tok0 + lr) * D_IN + kk + lc);
        float4 wv = *(const float4*)(w + (size_t)(g0  + lr) * D_IN + kk + lc);
        xs[lc + 0][lr] = xv.x; xs[lc + 1][lr] = xv.y; xs[lc + 2][lr] = xv.z; xs[lc + 3][lr] = xv.w;
        wsm[lc + 0][lr] = wv.x; wsm[lc + 1][lr] = wv.y; wsm[lc + 2][lr] = wv.z; wsm[lc + 3][lr] = wv.w;
        __syncthreads();
#pragma unroll
        for (int k = 0; k < 16; k++) {
            float4 a = *(const float4*)&xs[k][ty * 4];
            float4 b = *(const float4*)&wsm[k][tx * 4];
            float av[4] = {a.x, a.y, a.z, a.w};
            float bv[4] = {b.x, b.y, b.z, b.w};
#pragma unroll
            for (int i = 0; i < 4; i++)
#pragma unroll
                for (int j = 0; j < 4; j++)
                    acc[i][j] = fmaf(av[i], bv[j], acc[i][j]);
        }
        __syncthreads();
    }

    int g = g0 + tx * 4;
    float bb0 = b1[g + 0] + b2[g + 0];
    float bb1 = b1[g + 1] + b2[g + 1];
    float bb2 = b1[g + 2] + b2[g + 2];
    float bb3 = b1[g + 3] + b2[g + 3];
#pragma unroll
    for (int i = 0; i < 4; i++) {
        int tok = tok0 + ty * 4 + i;
        float4 o;
        o.x = acc[i][0] + bb0;
        o.y = acc[i][1] + bb1;
        o.z = acc[i][2] + bb2;
        o.w = acc[i][3] + bb3;
        *(float4*)(out + (size_t)tok * G4 + g) = o;
    }
}

// ---------------------------------------------------------------------------
// Kernel B: the sequential LSTM recurrence. One CTA per direction.
// Thread t owns gate row t (0..511). Weights: RK cols in registers,
// SK cols in shared memory ([col][thread] layout -> conflict-free LDS).
// ---------------------------------------------------------------------------
#define RK 80
#define SK 48
#define LSTM_SMEM ((SK * 512 + 128 + 512) * 4)

__global__ __launch_bounds__(512, 1) void lstm_kernel(
    const float* __restrict__ w_hh_f, const float* __restrict__ w_hh_b,
    const float* __restrict__ h0, const float* __restrict__ c0)
{
    extern __shared__ float sm[];
    float* ws   = sm;                 // [SK][512]
    float* h_sm = sm + SK * 512;      // [128]
    float* g_sm = h_sm + 128;         // [512]

    int dir = blockIdx.x;
    int t = threadIdx.x;
    const float* W = dir ? w_hh_b : w_hh_f;
    const float* Wrow = W + t * HH;

    // Register-resident weight columns
    float wr[RK];
#pragma unroll
    for (int k = 0; k < RK; k++) wr[k] = Wrow[k];
    // Shared-resident weight columns
#pragma unroll
    for (int c = 0; c < SK; c++) ws[c * 512 + t] = Wrow[RK + c];

    float c_reg = 0.f;
    if (t < HH) {
        h_sm[t] = h0[dir * HH + t];
        c_reg   = c0[dir * HH + t];
    }
    __syncthreads();

    const float* P = &g_pre[dir][0][0];
    int row    = dir ? (TT - 1) : 0;
    int stride = dir ? -1 : 1;

    float pre_cur = P[row * G4 + t];

    for (int step = 0; step < TT; step++) {
        // Prefetch next step's pre-activation (clamped index, branchless)
        int nrow = row + stride;
        int nc = nrow < 0 ? 0 : (nrow >= TT ? TT - 1 : nrow);
        float pre_next = P[nc * G4 + t];

        float a0 = pre_cur, a1 = 0.f, a2 = 0.f, a3 = 0.f;
#pragma unroll
        for (int k = 0; k < RK; k += 4) {
            a0 = fmaf(wr[k    ], h_sm[k    ], a0);
            a1 = fmaf(wr[k + 1], h_sm[k + 1], a1);
            a2 = fmaf(wr[k + 2], h_sm[k + 2], a2);
            a3 = fmaf(wr[k + 3], h_sm[k + 3], a3);
        }
#pragma unroll
        for (int c = 0; c < SK; c += 4) {
            a0 = fmaf(ws[(c + 0) * 512 + t], h_sm[RK + c + 0], a0);
            a1 = fmaf(ws[(c + 1) * 512 + t], h_sm[RK + c + 1], a1);
            a2 = fmaf(ws[(c + 2) * 512 + t], h_sm[RK + c + 2], a2);
            a3 = fmaf(ws[(c + 3) * 512 + t], h_sm[RK + c + 3], a3);
        }
        g_sm[t] = (a0 + a1) + (a2 + a3);
        __syncthreads();

        if (t < HH) {
            float gi = g_sm[t];
            float gf = g_sm[HH + t];
            float gg = g_sm[2 * HH + t];
            float go = g_sm[3 * HH + t];
            float iv = sigmoidf_(gi);
            float fv = sigmoidf_(gf);
            float gv = tanh_acc(gg);
            float ov = sigmoidf_(go);
            c_reg = fv * c_reg + iv * gv;
            float hv = ov * tanh_acc(c_reg);
            h_sm[t] = hv;
            int tt_idx = dir ? (TT - 1 - step) : step;
            g_hs[tt_idx][HH * dir + t] = hv;
        }
        __syncthreads();

        pre_cur = pre_next;
        row = nrow;
    }
}

// ---------------------------------------------------------------------------
// Kernel C: att[t] = sum_d tanh( (x @ w_omega)[t,d] ) * u_omega[d]
// 64 tokens/block, 256 threads (one per output dim d).
// ---------------------------------------------------------------------------
#define ATTN_SMEM ((64 * HID + 16 * 257) * 4)

__global__ __launch_bounds__(256) void attn_kernel(
    const float* __restrict__ w_omega, const float* __restrict__ u_omega)
{
    extern __shared__ float smc[];
    float* xs  = smc;               // [64*256] token-major
    float* red = smc + 64 * HID;    // [16][257]

    int tid  = threadIdx.x;
    int tok0 = blockIdx.x * 64;

    // Stage the 64-token x tile
    const float4* src = (const float4*)&g_hs[tok0][0];
    float4* dst = (float4*)xs;
    for (int idx = tid; idx < 64 * HID / 4; idx += 256) dst[idx] = src[idx];
    __syncthreads();

    float uo = u_omega[tid];

    for (int c = 0; c < 4; c++) {
        float acc[16];
#pragma unroll
        for (int t = 0; t < 16; t++) acc[t] = 0.f;
        const float* xbase = xs + (c * 16) * HID;

        for (int k = 0; k < HID; k += 4) {
            float w0 = __ldg(w_omega + (k + 0) * HID + tid);
            float w1 = __ldg(w_omega + (k + 1) * HID + tid);
            float w2 = __ldg(w_omega + (k + 2) * HID + tid);
            float w3 = __ldg(w_omega + (k + 3) * HID + tid);
#pragma unroll
            for (int t = 0; t < 16; t++) {
                float4 xv = *(const float4*)(xbase + t * HID + k);
                acc[t] = fmaf(xv.x, w0,
                         fmaf(xv.y, w1,
                         fmaf(xv.z, w2,
                         fmaf(xv.w, w3, acc[t]))));
            }
        }
#pragma unroll
        for (int t = 0; t < 16; t++)
            red[t * 257 + tid] = tanh_acc(acc[t]) * uo;
        __syncthreads();
        if (tid < 16) {
            float s = 0.f;
            for (int j = 0; j < HID; j++) s += red[tid * 257 + j];
            g_att[tok0 + c * 16 + tid] = s;
        }
        __syncthreads();
    }
}

// ---------------------------------------------------------------------------
// Kernel D: per-segment stable softmax over att, weighted-sum pooling of x,
// then tag projection. One block per segment (tensor_split semantics).
// ---------------------------------------------------------------------------
__global__ __launch_bounds__(256) void seg_pool_kernel(
    const int* __restrict__ mask,
    const float* __restrict__ w_tag, const float* __restrict__ b_tag,
    float* __restrict__ out)
{
    int s = blockIdx.x;
    int tid = threadIdx.x;
    int lo = (s == 0) ? 0 : mask[s - 1];
    int hi = (s == NSEG - 1) ? TT : mask[s];

    if (lo >= hi) {  // empty segment: context = 0 -> out = b_tag
        if (tid < TAGS) out[s * TAGS + tid] = b_tag[tid];
        return;
    }

    __shared__ float red[256];
    __shared__ float e_sm[256];
    __shared__ float ctx[256];

    // max
    float m = -3.4e38f;
    for (int i = lo + tid; i < hi; i += 256) m = fmaxf(m, g_att[i]);
    red[tid] = m; __syncthreads();
    for (int w = 128; w > 0; w >>= 1) {
        if (tid < w) red[tid] = fmaxf(red[tid], red[tid + w]);
        __syncthreads();
    }
    m = red[0]; __syncthreads();

    // sum of exp
    float z = 0.f;
    for (int i = lo + tid; i < hi; i += 256) z += __expf(g_att[i] - m);
    red[tid] = z; __syncthreads();
    for (int w = 128; w > 0; w >>= 1) {
        if (tid < w) red[tid] += red[tid + w];
        __syncthreads();
    }
    z = red[0]; __syncthreads();

    // weighted pooling: thread tid accumulates feature dim tid
    float acc = 0.f;
    for (int base = lo; base < hi; base += 256) {
        int i = base + tid;
        e_sm[tid] = (i < hi) ? __expf(g_att[i] - m) : 0.f;
        __syncthreads();
        int n = min(256, hi - base);
        for (int j = 0; j < n; j++)
            acc = fmaf(g_hs[base + j][tid], e_sm[j], acc);
        __syncthreads();
    }
    ctx[tid] = acc / z;
    __syncthreads();

    if (tid < TAGS) {
        float r = b_tag[tid];
        for (int d = 0; d < HID; d++) r = fmaf(ctx[d], w_tag[tid * HID + d], r);
        out[s * TAGS + tid] = r;
    }
}

// ---------------------------------------------------------------------------
extern "C" void kernel_launch(void* const* d_in, const int* in_sizes, int n_in,
                              void* d_out, int out_size)
{
    const float* sentence = (const float*)d_in[0];
    const float* h0       = (const float*)d_in[1];
    const float* c0       = (const float*)d_in[2];
    const float* w_ih_f   = (const float*)d_in[3];
    const float* w_hh_f   = (const float*)d_in[4];
    const float* b_ih_f   = (const float*)d_in[5];
    const float* b_hh_f   = (const float*)d_in[6];
    const float* w_ih_b   = (const float*)d_in[7];
    const float* w_hh_b   = (const float*)d_in[8];
    const float* b_ih_b   = (const float*)d_in[9];
    const float* b_hh_b   = (const float*)d_in[10];
    const float* w_omega  = (const float*)d_in[11];
    const float* u_omega  = (const float*)d_in[12];
    const float* w_tag    = (const float*)d_in[13];
    const float* b_tag    = (const float*)d_in[14];
    const int*   doc_mask = (const int*)d_in[15];
    float* out = (float*)d_out;

    cudaFuncSetAttribute(lstm_kernel, cudaFuncAttributeMaxDynamicSharedMemorySize, LSTM_SMEM);
    cudaFuncSetAttribute(attn_kernel, cudaFuncAttributeMaxDynamicSharedMemorySize, ATTN_SMEM);

    dim3 ggrid(TT / 64, G4 / 64, 2);
    gemm_pre_kernel<<<ggrid, 256>>>(sentence, w_ih_f, b_ih_f, b_hh_f,
                                    w_ih_b, b_ih_b, b_hh_b);
    lstm_kernel<<<2, 512, LSTM_SMEM>>>(w_hh_f, w_hh_b, h0, c0);
    attn_kernel<<<TT / 64, 256, ATTN_SMEM>>>(w_omega, u_omega);
    seg_pool_kernel<<<NSEG, 256>>>(doc_mask, w_tag, b_tag, out);
}

// round 3
// speedup vs baseline: 1.0176x; 1.0176x over previous
#include <cuda_runtime.h>
#include <math.h>

// Problem constants
#define TT   131072   // tokens
#define D_IN 256      // input dim
#define HH   128      // per-direction hidden
#define G4   512      // 4*HH gate rows
#define HID  256      // bidirectional hidden
#define TAGS 10
#define NSEG 1024

// Scratch (device globals — no allocation allowed in kernel_launch)
__device__ float g_pre[2][TT][G4];   // pre-activations per direction (original token order)
__device__ float g_hs[TT][HID];      // [hf | hb] concatenated
__device__ float g_att[TT];          // attention logits

__device__ __forceinline__ float sigmoidf_(float x) {
    return 1.0f / (1.0f + __expf(-x));
}
// Accurate tanh via expf, safe at +/- inf of the exp
__device__ __forceinline__ float tanh_acc(float x) {
    return 1.0f - 2.0f / (__expf(2.0f * x) + 1.0f);
}

// Packed dual-FMA (Blackwell f32x2). acc.{lo,hi} += a.{lo,hi} * b.{lo,hi}
__device__ __forceinline__ void ffma2(unsigned long long& acc,
                                      unsigned long long a,
                                      unsigned long long b) {
    asm("fma.rn.f32x2 %0, %1, %2, %0;" : "+l"(acc) : "l"(a), "l"(b));
}

// ---------------------------------------------------------------------------
// Kernel A: pre[dir][t][g] = x[t] . w_ih[g] + b_ih[g] + b_hh[g]
// 64x64 tile, K=256, 256 threads, 4x4 register blocking.
// ---------------------------------------------------------------------------
__global__ __launch_bounds__(256) void gemm_pre_kernel(
    const float* __restrict__ x,
    const float* __restrict__ wf, const float* __restrict__ bif, const float* __restrict__ bhf,
    const float* __restrict__ wb, const float* __restrict__ bib, const float* __restrict__ bhb)
{
    int dir = blockIdx.z;
    const float* w  = dir ? wb  : wf;
    const float* b1 = dir ? bib : bif;
    const float* b2 = dir ? bhb : bhf;
    float* out = &g_pre[dir][0][0];

    int tok0 = blockIdx.x * 64;
    int g0   = blockIdx.y * 64;

    __shared__ float xs[16][64];
    __shared__ float wsm[16][64];

    int tid = threadIdx.x;
    int tx = tid & 15;        // gate group
    int ty = tid >> 4;        // token group

    float acc[4][4];
#pragma unroll
    for (int i = 0; i < 4; i++)
#pragma unroll
        for (int j = 0; j < 4; j++) acc[i][j] = 0.f;

    int lr = tid >> 2;          // 0..63 (row within tile)
    int lc = (tid & 3) * 4;     // 0,4,8,12 (k offset)

    for (int kk = 0; kk < D_IN; kk += 16) {
        float4 xv = *(const float4*)(x + (size_t)(tok0 + lr) * D_IN + kk + lc);
        float4 wv = *(const float4*)(w + (size_t)(g0  + lr) * D_IN + kk + lc);
        xs[lc + 0][lr] = xv.x; xs[lc + 1][lr] = xv.y; xs[lc + 2][lr] = xv.z; xs[lc + 3][lr] = xv.w;
        wsm[lc + 0][lr] = wv.x; wsm[lc + 1][lr] = wv.y; wsm[lc + 2][lr] = wv.z; wsm[lc + 3][lr] = wv.w;
        __syncthreads();
#pragma unroll
        for (int k = 0; k < 16; k++) {
            float4 a = *(const float4*)&xs[k][ty * 4];
            float4 b = *(const float4*)&wsm[k][tx * 4];
            float av[4] = {a.x, a.y, a.z, a.w};
            float bv[4] = {b.x, b.y, b.z, b.w};
#pragma unroll
            for (int i = 0; i < 4; i++)
#pragma unroll
                for (int j = 0; j < 4; j++)
                    acc[i][j] = fmaf(av[i], bv[j], acc[i][j]);
        }
        __syncthreads();
    }

    int g = g0 + tx * 4;
    float bb0 = b1[g + 0] + b2[g + 0];
    float bb1 = b1[g + 1] + b2[g + 1];
    float bb2 = b1[g + 2] + b2[g + 2];
    float bb3 = b1[g + 3] + b2[g + 3];
#pragma unroll
    for (int i = 0; i < 4; i++) {
        int tok = tok0 + ty * 4 + i;
        float4 o;
        o.x = acc[i][0] + bb0;
        o.y = acc[i][1] + bb1;
        o.z = acc[i][2] + bb2;
        o.w = acc[i][3] + bb3;
        *(float4*)(out + (size_t)tok * G4 + g) = o;
    }
}

// ---------------------------------------------------------------------------
// Kernel B: sequential LSTM recurrence. One CTA per direction, 512 threads.
//
// Thread mapping: warp w (0..15) owns h indices j in [8w, 8w+8).
//   lane = gate*8 + jj  -> this thread computes gate row r = gate*128 + 8w + jj.
// All 4 gates of one h index live in ONE warp -> gates combine via shuffles,
// no g_sm staging, ONE __syncthreads per step (h double-buffered).
//
// Weights: 96 cols register-resident as packed f32x2 pairs, 32 cols in smem
// as ulonglong2 ([c4][512] layout -> conflict-free 16B LDS).
// Dot products use fma.rn.f32x2 (2 MACs / instruction).
// ---------------------------------------------------------------------------
#define RKC 96                       // register-resident columns
#define SKC 32                       // smem-resident columns
#define WS_U2 (SKC / 4)              // 8 ulonglong2 per thread
#define LSTM_SMEM (WS_U2 * 512 * 16 + 2 * HH * 4)

__global__ __launch_bounds__(512, 1) void lstm_kernel(
    const float* __restrict__ w_hh_f, const float* __restrict__ w_hh_b,
    const float* __restrict__ h0, const float* __restrict__ c0)
{
    extern __shared__ char smraw[];
    ulonglong2* ws = (ulonglong2*)smraw;                       // [WS_U2][512]
    float* hbuf = (float*)(smraw + WS_U2 * 512 * 16);          // [2][HH]

    int dir  = blockIdx.x;
    int t    = threadIdx.x;
    int w    = t >> 5;
    int lane = t & 31;
    int jj   = lane & 7;
    int j    = (w << 3) + jj;           // h index (0..127)
    int r    = ((lane >> 3) << 7) + j;  // gate row (0..511), gate = lane>>3

    const float* W = dir ? w_hh_b : w_hh_f;
    const ulonglong2* Wrow = (const ulonglong2*)(W + (size_t)r * HH);

    // Register weights: cols [0, 96) as 48 packed pairs
    unsigned long long wp[RKC / 2];
#pragma unroll
    for (int i = 0; i < RKC / 4; i++) {
        ulonglong2 v = Wrow[i];
        wp[2 * i]     = v.x;
        wp[2 * i + 1] = v.y;
    }
    // Smem weights: cols [96, 128)
#pragma unroll
    for (int c = 0; c < WS_U2; c++) ws[c * 512 + t] = Wrow[RKC / 4 + c];

    float c_reg = 0.f;
    if (t < HH) hbuf[t] = h0[dir * HH + t];
    if (lane < 8) c_reg = c0[dir * HH + j];
    __syncthreads();

    const float* P = &g_pre[dir][0][0];
    int row    = dir ? (TT - 1) : 0;
    int stride = dir ? -1 : 1;
    float pre_cur = P[(size_t)row * G4 + r];
    int p = 0;

    for (int step = 0; step < TT; step++) {
        // Prefetch next step's pre-activation (clamped, branchless)
        int nrow = row + stride;
        int ncl = nrow < 0 ? 0 : (nrow >= TT ? TT - 1 : nrow);
        float pre_next = __ldg(P + (size_t)ncl * G4 + r);

        const ulonglong2* hp = (const ulonglong2*)(hbuf + p * HH);

        unsigned long long accA, accB;
        asm("mov.b64 %0, {%1,%2};" : "=l"(accA) : "f"(pre_cur), "f"(0.0f));
        asm("mov.b64 %0, {%1,%2};" : "=l"(accB) : "f"(0.0f),    "f"(0.0f));

#pragma unroll
        for (int i = 0; i < RKC / 4; i++) {
            ulonglong2 hv = hp[i];
            ffma2(accA, wp[2 * i],     hv.x);
            ffma2(accB, wp[2 * i + 1], hv.y);
        }
#pragma unroll
        for (int c = 0; c < WS_U2; c++) {
            ulonglong2 wv = ws[c * 512 + t];
            ulonglong2 hv = hp[RKC / 4 + c];
            ffma2(accA, wv.x, hv.x);
            ffma2(accB, wv.y, hv.y);
        }

        float a0, a1, b0, b1;
        asm("mov.b64 {%0,%1}, %2;" : "=f"(a0), "=f"(a1) : "l"(accA));
        asm("mov.b64 {%0,%1}, %2;" : "=f"(b0), "=f"(b1) : "l"(accB));
        float v = (a0 + a1) + (b0 + b1);

        // Gather f, g, o gate values into the i-gate lanes (lanes 0..7)
        float gf = __shfl_sync(0xffffffffu, v, 8 + jj);
        float gg = __shfl_sync(0xffffffffu, v, 16 + jj);
        float go = __shfl_sync(0xffffffffu, v, 24 + jj);

        int np = p ^ 1;
        if (lane < 8) {
            float iv = sigmoidf_(v);
            float fv = sigmoidf_(gf);
            float gv = tanh_acc(gg);
            float ov = sigmoidf_(go);
            c_reg = fv * c_reg + iv * gv;
            float hv = ov * tanh_acc(c_reg);
            hbuf[np * HH + j] = hv;
            int tti = dir ? (TT - 1 - step) : step;
            g_hs[tti][HH * dir + j] = hv;
        }
        __syncthreads();

        p = np;
        pre_cur = pre_next;
        row = nrow;
    }
}

// ---------------------------------------------------------------------------
// Kernel C: att[t] = sum_d tanh( (x @ w_omega)[t,d] ) * u_omega[d]
// 64 tokens/block, 256 threads (one per output dim d).
// ---------------------------------------------------------------------------
#define ATTN_SMEM ((64 * HID + 16 * 257) * 4)

__global__ __launch_bounds__(256) void attn_kernel(
    const float* __restrict__ w_omega, const float* __restrict__ u_omega)
{
    extern __shared__ float smc[];
    float* xs  = smc;               // [64*256] token-major
    float* red = smc + 64 * HID;    // [16][257]

    int tid  = threadIdx.x;
    int tok0 = blockIdx.x * 64;

    // Stage the 64-token x tile
    const float4* src = (const float4*)&g_hs[tok0][0];
    float4* dst = (float4*)xs;
    for (int idx = tid; idx < 64 * HID / 4; idx += 256) dst[idx] = src[idx];
    __syncthreads();

    float uo = u_omega[tid];

    for (int c = 0; c < 4; c++) {
        float acc[16];
#pragma unroll
        for (int t = 0; t < 16; t++) acc[t] = 0.f;
        const float* xbase = xs + (c * 16) * HID;

        for (int k = 0; k < HID; k += 4) {
            float w0 = __ldg(w_omega + (k + 0) * HID + tid);
            float w1 = __ldg(w_omega + (k + 1) * HID + tid);
            float w2 = __ldg(w_omega + (k + 2) * HID + tid);
            float w3 = __ldg(w_omega + (k + 3) * HID + tid);
#pragma unroll
            for (int t = 0; t < 16; t++) {
                float4 xv = *(const float4*)(xbase + t * HID + k);
                acc[t] = fmaf(xv.x, w0,
                         fmaf(xv.y, w1,
                         fmaf(xv.z, w2,
                         fmaf(xv.w, w3, acc[t]))));
            }
        }
#pragma unroll
        for (int t = 0; t < 16; t++)
            red[t * 257 + tid] = tanh_acc(acc[t]) * uo;
        __syncthreads();
        if (tid < 16) {
            float s = 0.f;
            for (int j = 0; j < HID; j++) s += red[tid * 257 + j];
            g_att[tok0 + c * 16 + tid] = s;
        }
        __syncthreads();
    }
}

// ---------------------------------------------------------------------------
// Kernel D: per-segment stable softmax over att, weighted-sum pooling of x,
// then tag projection. One block per segment (tensor_split semantics).
// ---------------------------------------------------------------------------
__global__ __launch_bounds__(256) void seg_pool_kernel(
    const int* __restrict__ mask,
    const float* __restrict__ w_tag, const float* __restrict__ b_tag,
    float* __restrict__ out)
{
    int s = blockIdx.x;
    int tid = threadIdx.x;
    int lo = (s == 0) ? 0 : mask[s - 1];
    int hi = (s == NSEG - 1) ? TT : mask[s];

    if (lo >= hi) {  // empty segment: context = 0 -> out = b_tag
        if (tid < TAGS) out[s * TAGS + tid] = b_tag[tid];
        return;
    }

    __shared__ float red[256];
    __shared__ float e_sm[256];
    __shared__ float ctx[256];

    // max
    float m = -3.4e38f;
    for (int i = lo + tid; i < hi; i += 256) m = fmaxf(m, g_att[i]);
    red[tid] = m; __syncthreads();
    for (int w = 128; w > 0; w >>= 1) {
        if (tid < w) red[tid] = fmaxf(red[tid], red[tid + w]);
        __syncthreads();
    }
    m = red[0]; __syncthreads();

    // sum of exp
    float z = 0.f;
    for (int i = lo + tid; i < hi; i += 256) z += __expf(g_att[i] - m);
    red[tid] = z; __syncthreads();
    for (int w = 128; w > 0; w >>= 1) {
        if (tid < w) red[tid] += red[tid + w];
        __syncthreads();
    }
    z = red[0]; __syncthreads();

    // weighted pooling: thread tid accumulates feature dim tid
    float acc = 0.f;
    for (int base = lo; base < hi; base += 256) {
        int i = base + tid;
        e_sm[tid] = (i < hi) ? __expf(g_att[i] - m) : 0.f;
        __syncthreads();
        int n = min(256, hi - base);
        for (int jx = 0; jx < n; jx++)
            acc = fmaf(g_hs[base + jx][tid], e_sm[jx], acc);
        __syncthreads();
    }
    ctx[tid] = acc / z;
    __syncthreads();

    if (tid < TAGS) {
        float rr = b_tag[tid];
        for (int d = 0; d < HID; d++) rr = fmaf(ctx[d], w_tag[tid * HID + d], rr);
        out[s * TAGS + tid] = rr;
    }
}

// ---------------------------------------------------------------------------
extern "C" void kernel_launch(void* const* d_in, const int* in_sizes, int n_in,
                              void* d_out, int out_size)
{
    const float* sentence = (const float*)d_in[0];
    const float* h0       = (const float*)d_in[1];
    const float* c0       = (const float*)d_in[2];
    const float* w_ih_f   = (const float*)d_in[3];
    const float* w_hh_f   = (const float*)d_in[4];
    const float* b_ih_f   = (const float*)d_in[5];
    const float* b_hh_f   = (const float*)d_in[6];
    const float* w_ih_b   = (const float*)d_in[7];
    const float* w_hh_b   = (const float*)d_in[8];
    const float* b_ih_b   = (const float*)d_in[9];
    const float* b_hh_b   = (const float*)d_in[10];
    const float* w_omega  = (const float*)d_in[11];
    const float* u_omega  = (const float*)d_in[12];
    const float* w_tag    = (const float*)d_in[13];
    const float* b_tag    = (const float*)d_in[14];
    const int*   doc_mask = (const int*)d_in[15];
    float* out = (float*)d_out;

    cudaFuncSetAttribute(lstm_kernel, cudaFuncAttributeMaxDynamicSharedMemorySize, LSTM_SMEM);
    cudaFuncSetAttribute(attn_kernel, cudaFuncAttributeMaxDynamicSharedMemorySize, ATTN_SMEM);

    dim3 ggrid(TT / 64, G4 / 64, 2);
    gemm_pre_kernel<<<ggrid, 256>>>(sentence, w_ih_f, b_ih_f, b_hh_f,
                                    w_ih_b, b_ih_b, b_hh_b);
    lstm_kernel<<<2, 512, LSTM_SMEM>>>(w_hh_f, w_hh_b, h0, c0);
    attn_kernel<<<TT / 64, 256, ATTN_SMEM>>>(w_omega, u_omega);
    seg_pool_kernel<<<NSEG, 256>>>(doc_mask, w_tag, b_tag, out);
}